// round 5
// baseline (speedup 1.0000x reference)
#include <cuda_runtime.h>

#define NB    32
#define NMEL  128
#define TT    8192
#define NKEYS 88
#define NSLOT 57
#define TH    (TT/2)

// 57 distinct mel bins used by the 88 keys (validated: rel_err 0.0 in R1/R3/R4)
__device__ constexpr int DBIN[NSLOT] = {
   1,  2,  3,  4,  5,  6,  7,  8,  9, 10, 11, 12, 13, 14, 15, 16, 17,
  19, 20, 21, 22, 23, 25, 26, 28, 29, 31, 33, 35, 37, 39, 42,
  44, 46, 49, 51, 53, 56, 58, 60, 63,
  65, 68, 70, 72, 75, 77, 79, 82, 84, 86, 89, 91, 93, 96, 98, 101
};

// key -> distinct-slot index (non-decreasing)
__device__ constexpr int KS[NKEYS] = {
   0, 0, 0, 0, 0,
   1, 1, 1, 1, 1, 1, 1, 1, 1,
   2, 2, 2, 2, 2, 2,
   3, 3, 3, 3,
   4, 4, 4,  5, 5, 5,  6, 6, 6,
   7, 7,  8, 8,  9, 9,
  10, 11, 11, 12, 13, 14, 15, 16, 16,
  17, 18, 19, 20, 21, 22, 23, 24, 25, 26, 27, 28, 29, 30, 31, 32,
  33, 34, 35, 36, 37, 38, 39, 40, 41, 42, 43, 44, 45, 46, 47, 48,
  49, 50, 51, 52, 53, 54, 55, 56
};

// slot -> [first key, last key)
__device__ constexpr int KST[NSLOT + 1] = {
   0,  5, 14, 20, 24, 27, 30, 33, 35, 37, 39, 40, 42, 43, 44, 45, 46, 48,
  49, 50, 51, 52, 53, 54, 55, 56, 57, 58, 59, 60, 61, 62, 63, 64, 65, 66,
  67, 68, 69, 70, 71, 72, 73, 74, 75, 76, 77, 78, 79, 80, 81, 82, 83, 84,
  85, 86, 87, 88
};

__global__ void __launch_bounds__(128)
hps_key_probs_kernel(const float* __restrict__ mel,
                     float* __restrict__ out,
                     int write_two)
{
    const int q  = blockIdx.x * 128 + threadIdx.x;   // pair index 0..131071
    const int b  = q >> 12;                          // /4096 pairs per batch
    const int tp = (q & 4095) << 1;                  // first of 2 adjacent t

    // float2 view of this (b, t-pair) column; row r lives at m2[r * TH]
    const float2* __restrict__ m2 =
        (const float2*)(mel + (size_t)b * (NMEL * TT) + tp);

    // Log-domain HPS value of a bin for both t-lanes.
    auto loadw = [&](int bn) -> float2 {
        float2 s = m2[(size_t)bn * TH];
        if (bn < 64) { float2 a = m2[(size_t)(2 * bn) * TH]; s.x += a.x; s.y += a.y; }
        if (bn < 43) { float2 a = m2[(size_t)(3 * bn) * TH]; s.x += a.x; s.y += a.y; }
        return s;
    };

    const float NEG = __int_as_float(0xff800000);

    // ---- Phase 1: streaming top-16 of the 88-multiset, two t-lanes in
    // parallel, group values produced straight from gmem and consumed by the
    // sort network immediately (small live set).
    float tlo[16], thi[16], glo[16], ghi[16];

    #pragma unroll
    for (int grp = 0; grp < 6; ++grp) {
        #pragma unroll
        for (int u = 0; u < 16; ++u) {
            const int k = grp * 16 + u;
            if (k < NKEYS) {
                const float2 wv = loadw(DBIN[KS[k]]);
                glo[u] = wv.x; ghi[u] = wv.y;
            } else {
                glo[u] = NEG; ghi[u] = NEG;
            }
        }
        // bitonic sort g descending (compile-time lanes after unroll)
        #pragma unroll
        for (int kk = 2; kk <= 16; kk <<= 1) {
            #pragma unroll
            for (int j = kk >> 1; j > 0; j >>= 1) {
                #pragma unroll
                for (int i = 0; i < 16; ++i) {
                    const int l = i ^ j;
                    if (l > i) {
                        const float a0 = glo[i], c0 = glo[l];
                        const float a1 = ghi[i], c1 = ghi[l];
                        if ((i & kk) == 0) {
                            glo[i] = fmaxf(a0, c0); glo[l] = fminf(a0, c0);
                            ghi[i] = fmaxf(a1, c1); ghi[l] = fminf(a1, c1);
                        } else {
                            glo[i] = fminf(a0, c0); glo[l] = fmaxf(a0, c0);
                            ghi[i] = fminf(a1, c1); ghi[l] = fmaxf(a1, c1);
                        }
                    }
                }
            }
        }
        if (grp == 0) {
            #pragma unroll
            for (int i = 0; i < 16; ++i) { tlo[i] = glo[i]; thi[i] = ghi[i]; }
        } else {
            // merge-keep-top-16: max vs reversed g -> bitonic, then clean
            #pragma unroll
            for (int i = 0; i < 16; ++i) {
                tlo[i] = fmaxf(tlo[i], glo[15 - i]);
                thi[i] = fmaxf(thi[i], ghi[15 - i]);
            }
            #pragma unroll
            for (int j = 8; j > 0; j >>= 1) {
                #pragma unroll
                for (int i = 0; i < 16; ++i) {
                    const int l = i ^ j;
                    if (l > i) {
                        const float a0 = tlo[i], c0 = tlo[l];
                        const float a1 = thi[i], c1 = thi[l];
                        tlo[i] = fmaxf(a0, c0); tlo[l] = fminf(a0, c0);
                        thi[i] = fmaxf(a1, c1); thi[l] = fminf(a1, c1);
                    }
                }
            }
        }
    }

    // (v >= quantile(0.85)) <=> (log v >= 14th-largest log) = t[13]
    const float cutlo = tlo[13];
    const float cuthi = thi[13];

    // Compiler barrier: forbid CSE of phase-2 loads with phase-1 loads.
    // Without it ptxas keeps all 57 float2 slot values live across the whole
    // selection network (R4: 194 regs, occ 11%). Phase-2 reloads hit L1/L2
    // (block footprint 91KB), costing LSU issue only, not DRAM.
    asm volatile("" ::: "memory");

    float* o0 = out + (size_t)b * (NKEYS * TT) + tp;
    const size_t half = (size_t)NB * NKEYS * TT;

    // ---- Phase 2: recompute each distinct slot (bitwise-identical math),
    // compare, fan out STG.64 to its contiguous keys, both output copies.
    #pragma unroll
    for (int j = 0; j < NSLOT; ++j) {
        const float2 wv = loadw(DBIN[j]);
        float2 pv;
        pv.x = (wv.x >= cutlo) ? 1.0f : 0.0f;
        pv.y = (wv.y >= cuthi) ? 1.0f : 0.0f;
        #pragma unroll
        for (int k = KST[j]; k < KST[j + 1]; ++k) {
            *(float2*)(o0 + (size_t)k * TT) = pv;
            if (write_two) *(float2*)(o0 + (size_t)k * TT + half) = pv;
        }
    }
}

extern "C" void kernel_launch(void* const* d_in, const int* in_sizes, int n_in,
                              void* d_out, int out_size)
{
    const float* mel = (const float*)d_in[0];
    float* out = (float*)d_out;
    const long long half = (long long)NB * NKEYS * TT;   // 23,068,672
    const int write_two = (out_size >= 2 * half) ? 1 : 0;

    const int pairs = NB * TT / 2;       // 131072
    hps_key_probs_kernel<<<pairs / 128, 128>>>(mel, out, write_two);
}